// round 14
// baseline (speedup 1.0000x reference)
#include <cuda_runtime.h>

// SpatialGraphConv fused v3: fold-A-first, packed f32x2 FMA, persistent CTAs.
// 256 threads (2 warps/SMSP). GEMM warps split by output-channel half (no
// duplicated W traffic); warp-uniform xa reads vectorized via LDS.128.
//
// out[n,c,t,w] = sum_{kci} W[kci,c]*xa[n,t,kci,w] + sum_k b[k*128+c]*colsumA[k,w]
// xa[n,t,k*64+ci,w] = sum_v x[n,ci,t,v] * effA[k,v,w], effA = A*edge + adaptive_A

#define N_    64
#define CIN   64
#define T_    256
#define V_    25
#define K_    3
#define COUT  128
#define O_    384
#define KCI   192
#define TT    4
#define NWP   13            // live w-pairs (w 0..24, pair 12 half-live)
#define NWPP  14            // padded row stride in u64 (16B aligned)
#define THREADS 256
#define NTILES (N_ * (T_/TT))   // 4096

// ---- shared memory layout (float units) ----
#define WT_ROW 129
#define SM_WT   0
#define SM_WT_SZ (KCI*WT_ROW)                 // 24768 f
#define SM_XA   (SM_WT + SM_WT_SZ)            // u64[TT][KCI][NWPP] = 10752 u64
#define XA_U64  (TT*KCI*NWPP)
#define SM_XS   (SM_XA + 2*XA_U64)            // Xs[CIN][101] = 6464 f
#define XS_ROW  101
#define SM_XS_SZ (CIN*XS_ROW)
#define SM_EA   (SM_XS + SM_XS_SZ)            // effA2[K*V][NWPP] = 1050 u64
#define EA_U64  (K_*V_*NWPP)
#define SM_CS   (SM_EA + 2*EA_U64)            // colsum2[K][NWPP] = 42 u64
#define CS_U64  (K_*NWPP)
#define SM_B    (SM_CS + 2*CS_U64)            // b[384]
#define SM_TOTAL_F (SM_B + O_)                // 55304 f
#define SMEM_BYTES (SM_TOTAL_F * 4)           // 221216 B (<= 227KB opt-in)

typedef unsigned long long u64;

__device__ __forceinline__ u64 fma2(u64 a, u64 b, u64 c) {
    u64 d;
    asm("fma.rn.f32x2 %0, %1, %2, %3;" : "=l"(d) : "l"(a), "l"(b), "l"(c));
    return d;
}
__device__ __forceinline__ u64 pack2(float x, float y) {
    u64 d;
    asm("mov.b64 %0, {%1, %2};" : "=l"(d) : "f"(x), "f"(y));
    return d;
}
__device__ __forceinline__ float2 unpack2(u64 v) {
    float2 f;
    asm("mov.b64 {%0, %1}, %2;" : "=f"(f.x), "=f"(f.y) : "l"(v));
    return f;
}

extern __shared__ float smf[];

__global__ void __launch_bounds__(THREADS, 1)
sgc_kernel(const float* __restrict__ x, const float* __restrict__ Wg,
           const float* __restrict__ bg, const float* __restrict__ Ag,
           const float* __restrict__ eg, const float* __restrict__ dg,
           float* __restrict__ out)
{
    float* Wt = smf + SM_WT;                 // Wt[kci][c], row stride 129
    u64*   xa = (u64*)(smf + SM_XA);         // xa[tl][kci][wp], row stride 14
    float* Xs = smf + SM_XS;                 // Xs[ci][tl*25+v], row stride 101
    u64*   eA = (u64*)(smf + SM_EA);         // effA2[k*25+v][wp], stride 14
    u64*   cs = (u64*)(smf + SM_CS);         // colsum2[k][wp], stride 14
    float* bs = smf + SM_B;

    const int tid = threadIdx.x;

    // ---- one-time setup ----
    for (int idx = tid; idx < O_ * CIN; idx += THREADS) {
        int o  = idx >> 6;
        int ci = idx & 63;
        Wt[((o >> 7) * 64 + ci) * WT_ROW + (o & 127)] = Wg[idx];
    }
    for (int i = tid; i < O_; i += THREADS) bs[i] = bg[i];
    for (int i = tid; i < K_*V_*NWPP; i += THREADS) {
        int wp = i % NWPP;
        int kv = i / NWPP;                   // k*25 + v
        float e0 = 0.f, e1 = 0.f;
        if (wp < NWP) {
            int w0 = 2 * wp;
            e0 = Ag[kv*V_ + w0] * eg[kv*V_ + w0] + dg[kv*V_ + w0];
            if (w0 + 1 < V_)
                e1 = Ag[kv*V_ + w0+1] * eg[kv*V_ + w0+1] + dg[kv*V_ + w0+1];
        }
        eA[i] = pack2(e0, e1);
    }
    __syncthreads();
    for (int i = tid; i < CS_U64; i += THREADS) {
        int k = i / NWPP, wp = i % NWPP;
        float sx = 0.f, sy = 0.f;
        for (int v = 0; v < V_; v++) {
            float2 t = unpack2(eA[(k*V_ + v)*NWPP + wp]);
            sx += t.x; sy += t.y;
        }
        cs[i] = pack2(sx, sy);
    }
    __syncthreads();

    const int wid   = tid >> 5;       // 0..7
    const int lane  = tid & 31;
    const int tl    = wid & 3;        // t-slice for GEMM
    const int half  = wid >> 2;       // 0,1: output-channel half

    for (int tile = blockIdx.x; tile < NTILES; tile += gridDim.x) {
        const int n  = tile >> 6;
        const int t0 = (tile & 63) * TT;

        // ---- 1) stage X: Xs[ci][tsl*25+v] = x[n][ci][t0+tsl][v] ----
        const float* xg = x + (long)n * CIN * T_ * V_ + (long)t0 * V_;
        for (int idx = tid; idx < CIN * TT * V_; idx += THREADS) {
            int ci = idx / (TT * V_);
            int r  = idx % (TT * V_);
            Xs[ci * XS_ROW + r] = xg[(long)ci * T_ * V_ + r];
        }
        __syncthreads();

        // ---- 2) fold A: 24 units (tsl,k,r) over 8 warps, 3 each ----
        #pragma unroll
        for (int i = 0; i < 3; i++) {
            const int u   = wid + 8 * i;       // 0..23
            const int utl = u & 3;
            const int rem = u >> 2;            // 0..5
            const int k   = rem % 3;
            const int ci  = lane + 32 * (rem / 3);

            u64 acc[NWP];
            #pragma unroll
            for (int p = 0; p < NWP; p++) acc[p] = 0ull;

            const float* xr = &Xs[ci * XS_ROW + utl * V_];
            const u64*   ea = &eA[k * V_ * NWPP];
            #pragma unroll 5
            for (int v = 0; v < V_; v++) {
                float xv = xr[v];
                u64 xp = pack2(xv, xv);
                const ulonglong2* e2 = (const ulonglong2*)(ea + v * NWPP);
                #pragma unroll
                for (int q = 0; q < 6; q++) {
                    ulonglong2 ev = e2[q];            // uniform LDS.128
                    acc[2*q  ] = fma2(xp, ev.x, acc[2*q  ]);
                    acc[2*q+1] = fma2(xp, ev.y, acc[2*q+1]);
                }
                acc[12] = fma2(xp, ea[v * NWPP + 12], acc[12]);
            }
            u64* xw = &xa[((utl * KCI) + k * 64 + ci) * NWPP];
            #pragma unroll
            for (int p = 0; p < NWP; p++) xw[p] = acc[p];
        }
        __syncthreads();

        // ---- 3) GEMM: warp (tl,half); thread: c0=64*half+lane, c1=c0+32,
        //          all 13 wp; xa reads warp-uniform via LDS.128 ----
        u64 acc0[NWP], acc1[NWP];
        {
            const int c0 = 64 * half + lane;
            #pragma unroll
            for (int p = 0; p < NWP; p++) { acc0[p] = 0ull; acc1[p] = 0ull; }
            #pragma unroll
            for (int k = 0; k < K_; k++) {
                float b0 = bs[k * COUT + c0];
                float b1 = bs[k * COUT + c0 + 32];
                u64 b0p = pack2(b0, b0);
                u64 b1p = pack2(b1, b1);
                #pragma unroll
                for (int p = 0; p < NWP; p++) {
                    u64 cv = cs[k * NWPP + p];
                    acc0[p] = fma2(b0p, cv, acc0[p]);
                    acc1[p] = fma2(b1p, cv, acc1[p]);
                }
            }
            const float* wr = Wt + 64 * half + lane;
            const u64*   xr = xa + (long)tl * KCI * NWPP;
            #pragma unroll 2
            for (int kci = 0; kci < KCI; kci++) {
                float w0f = wr[0];
                float w1f = wr[32];
                u64 w0 = pack2(w0f, w0f);
                u64 w1 = pack2(w1f, w1f);
                const ulonglong2* x2 = (const ulonglong2*)xr;
                #pragma unroll
                for (int q = 0; q < 6; q++) {
                    ulonglong2 xv = x2[q];            // uniform LDS.128
                    acc0[2*q  ] = fma2(w0, xv.x, acc0[2*q  ]);
                    acc1[2*q  ] = fma2(w1, xv.x, acc1[2*q  ]);
                    acc0[2*q+1] = fma2(w0, xv.y, acc0[2*q+1]);
                    acc1[2*q+1] = fma2(w1, xv.y, acc1[2*q+1]);
                }
                u64 xv12 = xr[12];
                acc0[12] = fma2(w0, xv12, acc0[12]);
                acc1[12] = fma2(w1, xv12, acc1[12]);
                wr += WT_ROW;
                xr += NWPP;
            }
        }
        __syncthreads();   // all xa reads done -> reuse region as out stage

        // ---- 4) stage out: os[c][tsl*25+w], row 101 ----
        float* os = (float*)xa;      // 128*101 = 12928 f (region holds 21504)
        {
            const int c0 = 64 * half + lane;
            float* r0 = &os[c0 * 101 + tl * V_];
            float* r1 = &os[(c0 + 32) * 101 + tl * V_];
            #pragma unroll
            for (int p = 0; p < NWP; p++) {
                float2 a = unpack2(acc0[p]);
                float2 b = unpack2(acc1[p]);
                int w0i = 2 * p;
                r0[w0i] = a.x;
                r1[w0i] = b.x;
                if (w0i + 1 < V_) { r0[w0i + 1] = a.y; r1[w0i + 1] = b.y; }
            }
        }
        __syncthreads();

        // ---- 5) coalesced writeback ----
        float* og = out + (long)n * COUT * T_ * V_ + (long)t0 * V_;
        for (int idx = tid; idx < COUT * TT * V_; idx += THREADS) {
            int c = idx / (TT * V_);
            int r = idx % (TT * V_);
            og[(long)c * T_ * V_ + r] = os[c * 101 + r];
        }
        // no trailing barrier: program order (writeback before next stage-X)
        // + the barrier after stage-X orders os reads before xa overwrite.
    }
}

extern "C" void kernel_launch(void* const* d_in, const int* in_sizes, int n_in,
                              void* d_out, int out_size)
{
    (void)in_sizes; (void)n_in; (void)out_size;
    const float* x    = (const float*)d_in[0];
    const float* W    = (const float*)d_in[1];
    const float* b    = (const float*)d_in[2];
    const float* A    = (const float*)d_in[3];
    const float* edge = (const float*)d_in[4];
    const float* adp  = (const float*)d_in[5];
    float* out = (float*)d_out;

    int dev = 0, nsm = 0;
    cudaGetDevice(&dev);
    cudaDeviceGetAttribute(&nsm, cudaDevAttrMultiProcessorCount, dev);
    if (nsm <= 0) nsm = 148;
    cudaFuncSetAttribute(sgc_kernel,
                         cudaFuncAttributeMaxDynamicSharedMemorySize, SMEM_BYTES);

    sgc_kernel<<<nsm, THREADS, SMEM_BYTES>>>(x, W, b, A, edge, adp, out);
}

// round 15
// speedup vs baseline: 1.0052x; 1.0052x over previous
#include <cuda_runtime.h>

// SpatialGraphConv fused v3: fold-A-first, packed f32x2 FMA, persistent CTAs.
// 256 threads (2 warps/SMSP). GEMM warps split by output-channel half (no
// duplicated W traffic); warp-uniform xa reads vectorized via LDS.128.
//
// out[n,c,t,w] = sum_{kci} W[kci,c]*xa[n,t,kci,w] + sum_k b[k*128+c]*colsumA[k,w]
// xa[n,t,k*64+ci,w] = sum_v x[n,ci,t,v] * effA[k,v,w], effA = A*edge + adaptive_A

#define N_    64
#define CIN   64
#define T_    256
#define V_    25
#define K_    3
#define COUT  128
#define O_    384
#define KCI   192
#define TT    4
#define NWP   13            // live w-pairs (w 0..24, pair 12 half-live)
#define NWPP  14            // padded row stride in u64 (16B aligned)
#define THREADS 256
#define NTILES (N_ * (T_/TT))   // 4096

// ---- shared memory layout (float units) ----
#define WT_ROW 129
#define SM_WT   0
#define SM_WT_SZ (KCI*WT_ROW)                 // 24768 f
#define SM_XA   (SM_WT + SM_WT_SZ)            // u64[TT][KCI][NWPP] = 10752 u64
#define XA_U64  (TT*KCI*NWPP)
#define SM_XS   (SM_XA + 2*XA_U64)            // Xs[CIN][101] = 6464 f
#define XS_ROW  101
#define SM_XS_SZ (CIN*XS_ROW)
#define SM_EA   (SM_XS + SM_XS_SZ)            // effA2[K*V][NWPP] = 1050 u64
#define EA_U64  (K_*V_*NWPP)
#define SM_CS   (SM_EA + 2*EA_U64)            // colsum2[K][NWPP] = 42 u64
#define CS_U64  (K_*NWPP)
#define SM_B    (SM_CS + 2*CS_U64)            // b[384]
#define SM_TOTAL_F (SM_B + O_)                // 55304 f
#define SMEM_BYTES (SM_TOTAL_F * 4)           // 221216 B (<= 227KB opt-in)

typedef unsigned long long u64;

__device__ __forceinline__ u64 fma2(u64 a, u64 b, u64 c) {
    u64 d;
    asm("fma.rn.f32x2 %0, %1, %2, %3;" : "=l"(d) : "l"(a), "l"(b), "l"(c));
    return d;
}
__device__ __forceinline__ u64 pack2(float x, float y) {
    u64 d;
    asm("mov.b64 %0, {%1, %2};" : "=l"(d) : "f"(x), "f"(y));
    return d;
}
__device__ __forceinline__ float2 unpack2(u64 v) {
    float2 f;
    asm("mov.b64 {%0, %1}, %2;" : "=f"(f.x), "=f"(f.y) : "l"(v));
    return f;
}

extern __shared__ float smf[];

__global__ void __launch_bounds__(THREADS, 1)
sgc_kernel(const float* __restrict__ x, const float* __restrict__ Wg,
           const float* __restrict__ bg, const float* __restrict__ Ag,
           const float* __restrict__ eg, const float* __restrict__ dg,
           float* __restrict__ out)
{
    float* Wt = smf + SM_WT;                 // Wt[kci][c], row stride 129
    u64*   xa = (u64*)(smf + SM_XA);         // xa[tl][kci][wp], row stride 14
    float* Xs = smf + SM_XS;                 // Xs[ci][tl*25+v], row stride 101
    u64*   eA = (u64*)(smf + SM_EA);         // effA2[k*25+v][wp], stride 14
    u64*   cs = (u64*)(smf + SM_CS);         // colsum2[k][wp], stride 14
    float* bs = smf + SM_B;

    const int tid = threadIdx.x;

    // ---- one-time setup ----
    for (int idx = tid; idx < O_ * CIN; idx += THREADS) {
        int o  = idx >> 6;
        int ci = idx & 63;
        Wt[((o >> 7) * 64 + ci) * WT_ROW + (o & 127)] = Wg[idx];
    }
    for (int i = tid; i < O_; i += THREADS) bs[i] = bg[i];
    for (int i = tid; i < K_*V_*NWPP; i += THREADS) {
        int wp = i % NWPP;
        int kv = i / NWPP;                   // k*25 + v
        float e0 = 0.f, e1 = 0.f;
        if (wp < NWP) {
            int w0 = 2 * wp;
            e0 = Ag[kv*V_ + w0] * eg[kv*V_ + w0] + dg[kv*V_ + w0];
            if (w0 + 1 < V_)
                e1 = Ag[kv*V_ + w0+1] * eg[kv*V_ + w0+1] + dg[kv*V_ + w0+1];
        }
        eA[i] = pack2(e0, e1);
    }
    __syncthreads();
    for (int i = tid; i < CS_U64; i += THREADS) {
        int k = i / NWPP, wp = i % NWPP;
        float sx = 0.f, sy = 0.f;
        for (int v = 0; v < V_; v++) {
            float2 t = unpack2(eA[(k*V_ + v)*NWPP + wp]);
            sx += t.x; sy += t.y;
        }
        cs[i] = pack2(sx, sy);
    }
    __syncthreads();

    const int wid   = tid >> 5;       // 0..7
    const int lane  = tid & 31;
    const int tl    = wid & 3;        // t-slice for GEMM
    const int half  = wid >> 2;       // 0,1: output-channel half

    for (int tile = blockIdx.x; tile < NTILES; tile += gridDim.x) {
        const int n  = tile >> 6;
        const int t0 = (tile & 63) * TT;

        // ---- 1) stage X: Xs[ci][tsl*25+v] = x[n][ci][t0+tsl][v] ----
        const float* xg = x + (long)n * CIN * T_ * V_ + (long)t0 * V_;
        for (int idx = tid; idx < CIN * TT * V_; idx += THREADS) {
            int ci = idx / (TT * V_);
            int r  = idx % (TT * V_);
            Xs[ci * XS_ROW + r] = xg[(long)ci * T_ * V_ + r];
        }
        __syncthreads();

        // ---- 2) fold A: 24 units (tsl,k,r) over 8 warps, 3 each ----
        #pragma unroll
        for (int i = 0; i < 3; i++) {
            const int u   = wid + 8 * i;       // 0..23
            const int utl = u & 3;
            const int rem = u >> 2;            // 0..5
            const int k   = rem % 3;
            const int ci  = lane + 32 * (rem / 3);

            u64 acc[NWP];
            #pragma unroll
            for (int p = 0; p < NWP; p++) acc[p] = 0ull;

            const float* xr = &Xs[ci * XS_ROW + utl * V_];
            const u64*   ea = &eA[k * V_ * NWPP];
            #pragma unroll 5
            for (int v = 0; v < V_; v++) {
                float xv = xr[v];
                u64 xp = pack2(xv, xv);
                const ulonglong2* e2 = (const ulonglong2*)(ea + v * NWPP);
                #pragma unroll
                for (int q = 0; q < 6; q++) {
                    ulonglong2 ev = e2[q];            // uniform LDS.128
                    acc[2*q  ] = fma2(xp, ev.x, acc[2*q  ]);
                    acc[2*q+1] = fma2(xp, ev.y, acc[2*q+1]);
                }
                acc[12] = fma2(xp, ea[v * NWPP + 12], acc[12]);
            }
            u64* xw = &xa[((utl * KCI) + k * 64 + ci) * NWPP];
            #pragma unroll
            for (int p = 0; p < NWP; p++) xw[p] = acc[p];
        }
        __syncthreads();

        // ---- 3) GEMM: warp (tl,half); thread: c0=64*half+lane, c1=c0+32,
        //          all 13 wp; xa reads warp-uniform via LDS.128 ----
        u64 acc0[NWP], acc1[NWP];
        {
            const int c0 = 64 * half + lane;
            #pragma unroll
            for (int p = 0; p < NWP; p++) { acc0[p] = 0ull; acc1[p] = 0ull; }
            #pragma unroll
            for (int k = 0; k < K_; k++) {
                float b0 = bs[k * COUT + c0];
                float b1 = bs[k * COUT + c0 + 32];
                u64 b0p = pack2(b0, b0);
                u64 b1p = pack2(b1, b1);
                #pragma unroll
                for (int p = 0; p < NWP; p++) {
                    u64 cv = cs[k * NWPP + p];
                    acc0[p] = fma2(b0p, cv, acc0[p]);
                    acc1[p] = fma2(b1p, cv, acc1[p]);
                }
            }
            const float* wr = Wt + 64 * half + lane;
            const u64*   xr = xa + (long)tl * KCI * NWPP;
            #pragma unroll 2
            for (int kci = 0; kci < KCI; kci++) {
                float w0f = wr[0];
                float w1f = wr[32];
                u64 w0 = pack2(w0f, w0f);
                u64 w1 = pack2(w1f, w1f);
                const ulonglong2* x2 = (const ulonglong2*)xr;
                #pragma unroll
                for (int q = 0; q < 6; q++) {
                    ulonglong2 xv = x2[q];            // uniform LDS.128
                    acc0[2*q  ] = fma2(w0, xv.x, acc0[2*q  ]);
                    acc1[2*q  ] = fma2(w1, xv.x, acc1[2*q  ]);
                    acc0[2*q+1] = fma2(w0, xv.y, acc0[2*q+1]);
                    acc1[2*q+1] = fma2(w1, xv.y, acc1[2*q+1]);
                }
                u64 xv12 = xr[12];
                acc0[12] = fma2(w0, xv12, acc0[12]);
                acc1[12] = fma2(w1, xv12, acc1[12]);
                wr += WT_ROW;
                xr += NWPP;
            }
        }
        __syncthreads();   // all xa reads done -> reuse region as out stage

        // ---- 4) stage out: os[c][tsl*25+w], row 101 ----
        float* os = (float*)xa;      // 128*101 = 12928 f (region holds 21504)
        {
            const int c0 = 64 * half + lane;
            float* r0 = &os[c0 * 101 + tl * V_];
            float* r1 = &os[(c0 + 32) * 101 + tl * V_];
            #pragma unroll
            for (int p = 0; p < NWP; p++) {
                float2 a = unpack2(acc0[p]);
                float2 b = unpack2(acc1[p]);
                int w0i = 2 * p;
                r0[w0i] = a.x;
                r1[w0i] = b.x;
                if (w0i + 1 < V_) { r0[w0i + 1] = a.y; r1[w0i + 1] = b.y; }
            }
        }
        __syncthreads();

        // ---- 5) coalesced writeback ----
        float* og = out + (long)n * COUT * T_ * V_ + (long)t0 * V_;
        for (int idx = tid; idx < COUT * TT * V_; idx += THREADS) {
            int c = idx / (TT * V_);
            int r = idx % (TT * V_);
            og[(long)c * T_ * V_ + r] = os[c * 101 + r];
        }
        // no trailing barrier: program order (writeback before next stage-X)
        // + the barrier after stage-X orders os reads before xa overwrite.
    }
}

extern "C" void kernel_launch(void* const* d_in, const int* in_sizes, int n_in,
                              void* d_out, int out_size)
{
    (void)in_sizes; (void)n_in; (void)out_size;
    const float* x    = (const float*)d_in[0];
    const float* W    = (const float*)d_in[1];
    const float* b    = (const float*)d_in[2];
    const float* A    = (const float*)d_in[3];
    const float* edge = (const float*)d_in[4];
    const float* adp  = (const float*)d_in[5];
    float* out = (float*)d_out;

    int dev = 0, nsm = 0;
    cudaGetDevice(&dev);
    cudaDeviceGetAttribute(&nsm, cudaDevAttrMultiProcessorCount, dev);
    if (nsm <= 0) nsm = 148;
    cudaFuncSetAttribute(sgc_kernel,
                         cudaFuncAttributeMaxDynamicSharedMemorySize, SMEM_BYTES);

    sgc_kernel<<<nsm, THREADS, SMEM_BYTES>>>(x, W, b, A, edge, adp, out);
}